// round 2
// baseline (speedup 1.0000x reference)
#include <cuda_runtime.h>
#include <cstdint>

#define NN 100000
#define DIM 256
#define NE 500000

// Scratch message buffers (allocation-free rule: __device__ globals)
__device__ float g_msg1[(size_t)NN * DIM];
__device__ float g_msg2[(size_t)NN * DIM];

// ---------------------------------------------------------------------------
// Fused GEMM: [1.1*x@W_self -> d_out, x@W_r1 -> g_msg1, x@W_r2 -> g_msg2]
// 128x128 tile SGEMM, BK=16, 256 threads, 8x8 per-thread microtile.
// grid = (ceil(M/128), 6) : ntile 0,1 -> self ; 2,3 -> r1 ; 4,5 -> r2
// ---------------------------------------------------------------------------
__global__ __launch_bounds__(256) void gemm_cat(
    const float* __restrict__ x,
    const float* __restrict__ Ws,
    const float* __restrict__ W1,
    const float* __restrict__ W2,
    float* __restrict__ hout)
{
    __shared__ float As[16][128];
    __shared__ float Bs[16][128];

    const int mtile = blockIdx.x;
    const int ntile = blockIdx.y;
    const int rel   = ntile >> 1;
    const int ncol0 = (ntile & 1) << 7;

    const float* W    = (rel == 0) ? Ws   : (rel == 1) ? W1     : W2;
    float*       outp = (rel == 0) ? hout : (rel == 1) ? g_msg1 : g_msg2;
    const float scale = (rel == 0) ? 1.1f : 1.0f;

    const int tid  = threadIdx.x;
    const int tx   = tid & 15;   // 0..15 -> N
    const int ty   = tid >> 4;   // 0..15 -> M
    const int row0 = mtile * 128;

    float acc[8][8];
#pragma unroll
    for (int i = 0; i < 8; i++)
#pragma unroll
        for (int j = 0; j < 8; j++) acc[i][j] = 0.f;

    for (int k0 = 0; k0 < DIM; k0 += 16) {
        // A tile: 128 rows x 16 k, stored transposed As[k][m]
#pragma unroll
        for (int i = 0; i < 2; i++) {
            int idx = tid * 2 + i;          // 0..511
            int r   = idx >> 2;             // 0..127
            int c4  = idx & 3;              // float4 within 16 k
            int grow = row0 + r;
            float4 v = make_float4(0.f, 0.f, 0.f, 0.f);
            if (grow < NN)
                v = *reinterpret_cast<const float4*>(x + (size_t)grow * DIM + k0 + c4 * 4);
            As[c4 * 4 + 0][r] = v.x;
            As[c4 * 4 + 1][r] = v.y;
            As[c4 * 4 + 2][r] = v.z;
            As[c4 * 4 + 3][r] = v.w;
        }
        // B tile: 16 k x 128 n
#pragma unroll
        for (int i = 0; i < 2; i++) {
            int idx = tid * 2 + i;          // 0..511
            int kr  = idx >> 5;             // 0..15
            int c4  = idx & 31;             // 0..31
            float4 v = *reinterpret_cast<const float4*>(
                W + (size_t)(k0 + kr) * DIM + ncol0 + c4 * 4);
            *reinterpret_cast<float4*>(&Bs[kr][c4 * 4]) = v;
        }
        __syncthreads();

#pragma unroll
        for (int kk = 0; kk < 16; kk++) {
            float a[8], b[8];
#pragma unroll
            for (int i = 0; i < 8; i++) a[i] = As[kk][ty * 8 + i];
#pragma unroll
            for (int j = 0; j < 8; j++) b[j] = Bs[kk][tx * 8 + j];
#pragma unroll
            for (int i = 0; i < 8; i++)
#pragma unroll
                for (int j = 0; j < 8; j++)
                    acc[i][j] = fmaf(a[i], b[j], acc[i][j]);
        }
        __syncthreads();
    }

#pragma unroll
    for (int i = 0; i < 8; i++) {
        int grow = row0 + ty * 8 + i;
        if (grow < NN) {
            float* orow = outp + (size_t)grow * DIM + ncol0 + tx * 8;
#pragma unroll
            for (int j = 0; j < 8; j += 4) {
                float4 v;
                v.x = acc[i][j + 0] * scale;
                v.y = acc[i][j + 1] * scale;
                v.z = acc[i][j + 2] * scale;
                v.w = acc[i][j + 3] * scale;
                *reinterpret_cast<float4*>(orow + j) = v;
            }
        }
    }
}

// ---------------------------------------------------------------------------
// Edge scatter: one warp per edge; gather msg[src] row (1KB), red.add into
// h[dst]. blockIdx.y selects the relation (uniform per block).
// ---------------------------------------------------------------------------
__device__ __forceinline__ void red_add_v4(float4* p, float4 v) {
    asm volatile("red.global.add.v4.f32 [%0], {%1,%2,%3,%4};"
                 :: "l"(p), "f"(v.x), "f"(v.y), "f"(v.z), "f"(v.w)
                 : "memory");
}

__global__ __launch_bounds__(256) void edge_scatter(
    const int* __restrict__ src1, const int* __restrict__ dst1,
    const int* __restrict__ src2, const int* __restrict__ dst2,
    float* __restrict__ h)
{
    int e    = (blockIdx.x * 256 + threadIdx.x) >> 5;   // edge id within relation
    int lane = threadIdx.x & 31;
    if (e >= NE) return;

    const int* src; const int* dst; const float* msg;
    if (blockIdx.y == 0) { src = src1; dst = dst1; msg = g_msg1; }
    else                 { src = src2; dst = dst2; msg = g_msg2; }

    int s = __ldg(src + e);
    int d = __ldg(dst + e);

    const float4* sp = reinterpret_cast<const float4*>(msg + (size_t)s * DIM);
    float4*       dp = reinterpret_cast<float4*>(h + (size_t)d * DIM);

    float4 v0 = sp[lane];
    float4 v1 = sp[lane + 32];
    red_add_v4(dp + lane,      v0);
    red_add_v4(dp + lane + 32, v1);
}

// ---------------------------------------------------------------------------
// Epilogue: h = relu(h + bias)  (relu applied twice in ref == once)
// ---------------------------------------------------------------------------
__global__ __launch_bounds__(256) void bias_relu(
    float* __restrict__ h, const float* __restrict__ bias)
{
    int i = blockIdx.x * 256 + threadIdx.x;       // float4 index
    if (i >= NN * (DIM / 4)) return;
    int c4 = i & (DIM / 4 - 1);
    float4 b = __ldg(reinterpret_cast<const float4*>(bias) + c4);
    float4 v = reinterpret_cast<float4*>(h)[i];
    v.x = fmaxf(v.x + b.x, 0.f);
    v.y = fmaxf(v.y + b.y, 0.f);
    v.z = fmaxf(v.z + b.z, 0.f);
    v.w = fmaxf(v.w + b.w, 0.f);
    reinterpret_cast<float4*>(h)[i] = v;
}

// ---------------------------------------------------------------------------
extern "C" void kernel_launch(void* const* d_in, const int* in_sizes, int n_in,
                              void* d_out, int out_size)
{
    const float* x    = (const float*)d_in[0];
    const float* Ws   = (const float*)d_in[1];
    const float* W1   = (const float*)d_in[2];
    const float* W2   = (const float*)d_in[3];
    const float* bias = (const float*)d_in[4];
    const int* src1   = (const int*)d_in[5];
    const int* dst1   = (const int*)d_in[6];
    const int* src2   = (const int*)d_in[7];
    const int* dst2   = (const int*)d_in[8];
    float* h = (float*)d_out;

    dim3 ggrid((NN + 127) / 128, 6);
    gemm_cat<<<ggrid, 256>>>(x, Ws, W1, W2, h);

    dim3 egrid((NE * 32 + 255) / 256, 2);
    edge_scatter<<<egrid, 256>>>(src1, dst1, src2, dst2, h);

    int q = NN * (DIM / 4);
    bias_relu<<<(q + 255) / 256, 256>>>(h, bias);
}

// round 7
// speedup vs baseline: 1.9441x; 1.9441x over previous
#include <cuda_runtime.h>
#include <cuda_bf16.h>
#include <cstdint>

#define NN 100000
#define DIM 256
#define NE 500000
#define MTILES 782            // ceil(NN/128)

// ---------------------------------------------------------------------------
// __device__ global scratch (allocation-free rule)
// ---------------------------------------------------------------------------
__device__ float g_msg1[(size_t)NN * DIM];
__device__ float g_msg2[(size_t)NN * DIM];
__device__ __nv_bfloat16 g_xhi[(size_t)NN * DIM];
__device__ __nv_bfloat16 g_xlo[(size_t)NN * DIM];
__device__ __nv_bfloat16 g_whi[3 * DIM * DIM];   // [rel][n][k], 1.1 folded into rel 0
__device__ __nv_bfloat16 g_wlo[3 * DIM * DIM];

// ---------------------------------------------------------------------------
// PTX helpers (baseline ISA only — no 'a' features; harness targets compute_103)
// ---------------------------------------------------------------------------
__device__ __forceinline__ uint32_t smem_u32(const void* p) {
    uint32_t a;
    asm("{ .reg .u64 t; cvta.to.shared.u64 t, %1; cvt.u32.u64 %0, t; }"
        : "=r"(a) : "l"(p));
    return a;
}

#define CP_ASYNC16(dst, src) \
    asm volatile("cp.async.cg.shared.global [%0], [%1], 16;" :: "r"(dst), "l"(src))
#define CP_COMMIT() asm volatile("cp.async.commit_group;" ::: "memory")
#define CP_WAIT(n)  asm volatile("cp.async.wait_group %0;" :: "n"(n) : "memory")

#define LDSM_X4(r, addr) \
    asm volatile("ldmatrix.sync.aligned.m8n8.x4.shared.b16 {%0,%1,%2,%3}, [%4];" \
        : "=r"((r)[0]), "=r"((r)[1]), "=r"((r)[2]), "=r"((r)[3]) : "r"(addr))

#define MMA16816(d, a, b0, b1) \
    asm volatile("mma.sync.aligned.m16n8k16.row.col.f32.bf16.bf16.f32 " \
        "{%0,%1,%2,%3}, {%4,%5,%6,%7}, {%8,%9}, {%0,%1,%2,%3};" \
        : "+f"((d)[0]), "+f"((d)[1]), "+f"((d)[2]), "+f"((d)[3]) \
        : "r"((a)[0]), "r"((a)[1]), "r"((a)[2]), "r"((a)[3]), "r"(b0), "r"(b1))

// ---------------------------------------------------------------------------
// Prep: split x into bf16 hi/lo
// ---------------------------------------------------------------------------
__global__ __launch_bounds__(256) void split_x(const float* __restrict__ x) {
    size_t i = (size_t)blockIdx.x * 256 + threadIdx.x;   // per float4
    if (i >= (size_t)NN * DIM / 4) return;
    float4 v = reinterpret_cast<const float4*>(x)[i];
    __nv_bfloat16 h0 = __float2bfloat16(v.x), h1 = __float2bfloat16(v.y);
    __nv_bfloat16 h2 = __float2bfloat16(v.z), h3 = __float2bfloat16(v.w);
    __nv_bfloat16 l0 = __float2bfloat16(v.x - __bfloat162float(h0));
    __nv_bfloat16 l1 = __float2bfloat16(v.y - __bfloat162float(h1));
    __nv_bfloat16 l2 = __float2bfloat16(v.z - __bfloat162float(h2));
    __nv_bfloat16 l3 = __float2bfloat16(v.w - __bfloat162float(h3));
    reinterpret_cast<__nv_bfloat162*>(g_xhi)[2 * i]     = __nv_bfloat162(h0, h1);
    reinterpret_cast<__nv_bfloat162*>(g_xhi)[2 * i + 1] = __nv_bfloat162(h2, h3);
    reinterpret_cast<__nv_bfloat162*>(g_xlo)[2 * i]     = __nv_bfloat162(l0, l1);
    reinterpret_cast<__nv_bfloat162*>(g_xlo)[2 * i + 1] = __nv_bfloat162(l2, l3);
}

// Prep: transpose + split W  (g_w*[rel*65536 + n*256 + k] = split(Weff[k][n]))
__global__ __launch_bounds__(256) void split_w(
    const float* __restrict__ Ws, const float* __restrict__ W1,
    const float* __restrict__ W2)
{
    int idx = blockIdx.x * 256 + threadIdx.x;            // 0 .. 196607
    if (idx >= 3 * DIM * DIM) return;
    int rel = idx >> 16;
    int r   = idx & 65535;
    int n   = r >> 8;
    int k   = r & 255;
    const float* W = (rel == 0) ? Ws : (rel == 1) ? W1 : W2;
    float v = W[k * DIM + n] * ((rel == 0) ? 1.1f : 1.0f);
    __nv_bfloat16 hi = __float2bfloat16(v);
    __nv_bfloat16 lo = __float2bfloat16(v - __bfloat162float(hi));
    g_whi[idx] = hi;
    g_wlo[idx] = lo;
}

// ---------------------------------------------------------------------------
// HMMA GEMM: 128x128 tile/CTA, K_eff = 3x256 (hi*hi + hi*lo + lo*hi).
// 8 warps, each 32(M)x64(N). cp.async double-buffered 64-K chunks.
// SMEM chunk layout per operand: 128 rows x 128B (64 bf16), XOR-swizzled.
// grid (782, 6): rel = ntile>>1, n0 = (ntile&1)*128.
// ---------------------------------------------------------------------------
#define CHUNK_BYTES (128 * 128)            // 16KB per operand chunk
#define BUF_BYTES   (2 * CHUNK_BYTES)      // A + B
#define GEMM_SMEM   (2 * BUF_BYTES)        // double buffer = 64KB

__global__ __launch_bounds__(256) void gemm_mma(float* __restrict__ h)
{
    extern __shared__ __align__(128) char smem[];
    const int tid    = threadIdx.x;
    const int wid    = tid >> 5, lane = tid & 31;
    const int warp_m = wid & 3;        // 4 x 32 rows
    const int warp_n = wid >> 2;       // 2 x 64 cols
    const int mtile  = blockIdx.x, ntile = blockIdx.y;
    const int rel    = ntile >> 1, n0 = (ntile & 1) << 7;
    const int row0   = mtile * 128;

    uint32_t sbase = smem_u32(smem);

    const char* Ahi = (const char*)g_xhi;
    const char* Alo = (const char*)g_xlo;
    const char* Bhi = (const char*)g_whi + (size_t)rel * 131072;
    const char* Blo = (const char*)g_wlo + (size_t)rel * 131072;

    float acc[2][8][4];
#pragma unroll
    for (int mt = 0; mt < 2; mt++)
#pragma unroll
        for (int nt = 0; nt < 8; nt++)
#pragma unroll
            for (int q = 0; q < 4; q++) acc[mt][nt][q] = 0.f;

    // chunk c in 0..11: seg = c>>2 selects (A,B) source pair, kc = c&3 the 64-K slice
    auto load_chunk = [&](int c, int bsel) {
        int seg = c >> 2, kc = c & 3;
        const char* As = (seg == 2) ? Alo : Ahi;
        const char* Bs = (seg == 1) ? Blo : Bhi;
        uint32_t bb = sbase + bsel * BUF_BYTES;
#pragma unroll
        for (int q = 0; q < 8; q++) {
            int s    = tid + (q << 8);          // 0..2047 16B segments
            int part = s >> 10;                 // 0:A 1:B
            int s10  = s & 1023;
            int row  = s10 >> 3;                // 0..127
            int j    = s10 & 7;                 // 16B seg within 128B row
            uint32_t dst = bb + part * CHUNK_BYTES + row * 128 + ((j ^ (row & 7)) << 4);
            const char* src;
            if (part == 0) {
                int gr = row0 + row; if (gr >= NN) gr = NN - 1;
                src = As + (size_t)gr * 512 + kc * 128 + j * 16;
            } else {
                src = Bs + (size_t)(n0 + row) * 512 + kc * 128 + j * 16;
            }
            CP_ASYNC16(dst, src);
        }
        CP_COMMIT();
    };

    load_chunk(0, 0);

    for (int c = 0; c < 12; c++) {
        int b = c & 1;
        if (c + 1 < 12) { load_chunk(c + 1, 1 - b); CP_WAIT(1); }
        else            { CP_WAIT(0); }
        __syncthreads();

        uint32_t Ab = sbase + b * BUF_BYTES;
        uint32_t Bb = Ab + CHUNK_BYTES;

#pragma unroll
        for (int ks = 0; ks < 4; ks++) {         // K=16 steps within 64-K chunk
            uint32_t a[2][4];
#pragma unroll
            for (int mt = 0; mt < 2; mt++) {
                int r = warp_m * 32 + mt * 16 + (lane & 15);
                int j = ks * 2 + (lane >> 4);
                LDSM_X4(a[mt], Ab + r * 128 + ((j ^ (r & 7)) << 4));
            }
            uint32_t bf[4][4];                   // nt2: 2 adjacent n8 tiles each
#pragma unroll
            for (int nt2 = 0; nt2 < 4; nt2++) {
                int g = lane >> 3;
                int n = warp_n * 64 + nt2 * 16 + ((g >> 1) << 3) + (lane & 7);
                int j = ks * 2 + (g & 1);
                LDSM_X4(bf[nt2], Bb + n * 128 + ((j ^ (n & 7)) << 4));
            }
#pragma unroll
            for (int mt = 0; mt < 2; mt++)
#pragma unroll
                for (int nt2 = 0; nt2 < 4; nt2++) {
                    MMA16816(acc[mt][nt2 * 2],     a[mt], bf[nt2][0], bf[nt2][1]);
                    MMA16816(acc[mt][nt2 * 2 + 1], a[mt], bf[nt2][2], bf[nt2][3]);
                }
        }
        __syncthreads();   // buffer b is recycled by load at iteration c+1
    }

    float* outp = (rel == 0) ? h : (rel == 1 ? g_msg1 : g_msg2);
#pragma unroll
    for (int mt = 0; mt < 2; mt++) {
        int r = row0 + warp_m * 32 + mt * 16 + (lane >> 2);
#pragma unroll
        for (int nt = 0; nt < 8; nt++) {
            int colb = n0 + warp_n * 64 + nt * 8 + 2 * (lane & 3);
            if (r < NN)
                *reinterpret_cast<float2*>(outp + (size_t)r * DIM + colb) =
                    make_float2(acc[mt][nt][0], acc[mt][nt][1]);
            if (r + 8 < NN)
                *reinterpret_cast<float2*>(outp + (size_t)(r + 8) * DIM + colb) =
                    make_float2(acc[mt][nt][2], acc[mt][nt][3]);
        }
    }
}

// ---------------------------------------------------------------------------
// Edge scatter: one warp per edge; gather msg[src] row, red.add into h[dst].
// ---------------------------------------------------------------------------
__device__ __forceinline__ void red_add_v4(float4* p, float4 v) {
    asm volatile("red.global.add.v4.f32 [%0], {%1,%2,%3,%4};"
                 :: "l"(p), "f"(v.x), "f"(v.y), "f"(v.z), "f"(v.w)
                 : "memory");
}

__global__ __launch_bounds__(256) void edge_scatter(
    const int* __restrict__ src1, const int* __restrict__ dst1,
    const int* __restrict__ src2, const int* __restrict__ dst2,
    float* __restrict__ h)
{
    int e    = (blockIdx.x * 256 + threadIdx.x) >> 5;
    int lane = threadIdx.x & 31;
    if (e >= NE) return;

    const int* src; const int* dst; const float* msg;
    if (blockIdx.y == 0) { src = src1; dst = dst1; msg = g_msg1; }
    else                 { src = src2; dst = dst2; msg = g_msg2; }

    int s = __ldg(src + e);
    int d = __ldg(dst + e);
    const float4* sp = reinterpret_cast<const float4*>(msg + (size_t)s * DIM);
    float4*       dp = reinterpret_cast<float4*>(h + (size_t)d * DIM);
    float4 v0 = sp[lane];
    float4 v1 = sp[lane + 32];
    red_add_v4(dp + lane,      v0);
    red_add_v4(dp + lane + 32, v1);
}

// ---------------------------------------------------------------------------
// Epilogue: h = relu(h + bias)
// ---------------------------------------------------------------------------
__global__ __launch_bounds__(256) void bias_relu(
    float* __restrict__ h, const float* __restrict__ bias)
{
    int i = blockIdx.x * 256 + threadIdx.x;
    if (i >= NN * (DIM / 4)) return;
    int c4 = i & (DIM / 4 - 1);
    float4 b = __ldg(reinterpret_cast<const float4*>(bias) + c4);
    float4 v = reinterpret_cast<float4*>(h)[i];
    v.x = fmaxf(v.x + b.x, 0.f);
    v.y = fmaxf(v.y + b.y, 0.f);
    v.z = fmaxf(v.z + b.z, 0.f);
    v.w = fmaxf(v.w + b.w, 0.f);
    reinterpret_cast<float4*>(h)[i] = v;
}

// ---------------------------------------------------------------------------
extern "C" void kernel_launch(void* const* d_in, const int* in_sizes, int n_in,
                              void* d_out, int out_size)
{
    const float* x    = (const float*)d_in[0];
    const float* Ws   = (const float*)d_in[1];
    const float* W1   = (const float*)d_in[2];
    const float* W2   = (const float*)d_in[3];
    const float* bias = (const float*)d_in[4];
    const int* src1   = (const int*)d_in[5];
    const int* dst1   = (const int*)d_in[6];
    const int* src2   = (const int*)d_in[7];
    const int* dst2   = (const int*)d_in[8];
    float* h = (float*)d_out;

    cudaFuncSetAttribute(gemm_mma, cudaFuncAttributeMaxDynamicSharedMemorySize, GEMM_SMEM);

    int nx = (int)(((size_t)NN * DIM / 4 + 255) / 256);
    split_x<<<nx, 256>>>(x);
    split_w<<<(3 * DIM * DIM + 255) / 256, 256>>>(Ws, W1, W2);

    dim3 ggrid(MTILES, 6);
    gemm_mma<<<ggrid, 256, GEMM_SMEM>>>(h);

    dim3 egrid((NE * 32 + 255) / 256, 2);
    edge_scatter<<<egrid, 256>>>(src1, dst1, src2, dst2, h);

    int q = NN * (DIM / 4);
    bias_relu<<<(q + 255) / 256, 256>>>(h, bias);
}

// round 8
// speedup vs baseline: 2.3993x; 1.2341x over previous
#include <cuda_runtime.h>
#include <cuda_bf16.h>
#include <cstdint>

#define NN 100000
#define DIM 256
#define NE 500000
#define MTILES 782            // ceil(NN/128)
#define CAP 64                // bucket capacity per (rel, node); fallback if exceeded

// ---------------------------------------------------------------------------
// __device__ global scratch (allocation-free rule)
// ---------------------------------------------------------------------------
__device__ float g_msg1[(size_t)NN * DIM];
__device__ float g_msg2[(size_t)NN * DIM];
__device__ __nv_bfloat16 g_xhi[(size_t)NN * DIM];
__device__ __nv_bfloat16 g_xlo[(size_t)NN * DIM];
__device__ __nv_bfloat16 g_whi[3 * DIM * DIM];   // [rel][n][k], 1.1 folded into rel 0
__device__ __nv_bfloat16 g_wlo[3 * DIM * DIM];
__device__ int g_cnt[2 * NN];
__device__ int g_bkt[(size_t)2 * NN * CAP];

// ---------------------------------------------------------------------------
// PTX helpers (baseline ISA only — harness targets compute_103, no 'a' features)
// ---------------------------------------------------------------------------
__device__ __forceinline__ uint32_t smem_u32(const void* p) {
    uint32_t a;
    asm("{ .reg .u64 t; cvta.to.shared.u64 t, %1; cvt.u32.u64 %0, t; }"
        : "=r"(a) : "l"(p));
    return a;
}

#define CP_ASYNC16(dst, src) \
    asm volatile("cp.async.cg.shared.global [%0], [%1], 16;" :: "r"(dst), "l"(src))
#define CP_COMMIT() asm volatile("cp.async.commit_group;" ::: "memory")
#define CP_WAIT(n)  asm volatile("cp.async.wait_group %0;" :: "n"(n) : "memory")

#define LDSM_X4(r, addr) \
    asm volatile("ldmatrix.sync.aligned.m8n8.x4.shared.b16 {%0,%1,%2,%3}, [%4];" \
        : "=r"((r)[0]), "=r"((r)[1]), "=r"((r)[2]), "=r"((r)[3]) : "r"(addr))

#define MMA16816(d, a, b0, b1) \
    asm volatile("mma.sync.aligned.m16n8k16.row.col.f32.bf16.bf16.f32 " \
        "{%0,%1,%2,%3}, {%4,%5,%6,%7}, {%8,%9}, {%0,%1,%2,%3};" \
        : "+f"((d)[0]), "+f"((d)[1]), "+f"((d)[2]), "+f"((d)[3]) \
        : "r"((a)[0]), "r"((a)[1]), "r"((a)[2]), "r"((a)[3]), "r"(b0), "r"(b1))

__device__ __forceinline__ void red_add_v4(float4* p, float4 v) {
    asm volatile("red.global.add.v4.f32 [%0], {%1,%2,%3,%4};"
                 :: "l"(p), "f"(v.x), "f"(v.y), "f"(v.z), "f"(v.w)
                 : "memory");
}

// ---------------------------------------------------------------------------
// Prep: split x into bf16 hi/lo
// ---------------------------------------------------------------------------
__global__ __launch_bounds__(256) void split_x(const float* __restrict__ x) {
    size_t i = (size_t)blockIdx.x * 256 + threadIdx.x;   // per float4
    if (i >= (size_t)NN * DIM / 4) return;
    float4 v = reinterpret_cast<const float4*>(x)[i];
    __nv_bfloat16 h0 = __float2bfloat16(v.x), h1 = __float2bfloat16(v.y);
    __nv_bfloat16 h2 = __float2bfloat16(v.z), h3 = __float2bfloat16(v.w);
    __nv_bfloat16 l0 = __float2bfloat16(v.x - __bfloat162float(h0));
    __nv_bfloat16 l1 = __float2bfloat16(v.y - __bfloat162float(h1));
    __nv_bfloat16 l2 = __float2bfloat16(v.z - __bfloat162float(h2));
    __nv_bfloat16 l3 = __float2bfloat16(v.w - __bfloat162float(h3));
    reinterpret_cast<__nv_bfloat162*>(g_xhi)[2 * i]     = __nv_bfloat162(h0, h1);
    reinterpret_cast<__nv_bfloat162*>(g_xhi)[2 * i + 1] = __nv_bfloat162(h2, h3);
    reinterpret_cast<__nv_bfloat162*>(g_xlo)[2 * i]     = __nv_bfloat162(l0, l1);
    reinterpret_cast<__nv_bfloat162*>(g_xlo)[2 * i + 1] = __nv_bfloat162(l2, l3);
}

// Prep: transpose + split W  (g_w*[rel*65536 + n*256 + k] = split(Weff[k][n]))
__global__ __launch_bounds__(256) void split_w(
    const float* __restrict__ Ws, const float* __restrict__ W1,
    const float* __restrict__ W2)
{
    int idx = blockIdx.x * 256 + threadIdx.x;            // 0 .. 196607
    if (idx >= 3 * DIM * DIM) return;
    int rel = idx >> 16;
    int r   = idx & 65535;
    int n   = r >> 8;
    int k   = r & 255;
    const float* W = (rel == 0) ? Ws : (rel == 1) ? W1 : W2;
    float v = W[k * DIM + n] * ((rel == 0) ? 1.1f : 1.0f);
    __nv_bfloat16 hi = __float2bfloat16(v);
    __nv_bfloat16 lo = __float2bfloat16(v - __bfloat162float(hi));
    g_whi[idx] = hi;
    g_wlo[idx] = lo;
}

// ---------------------------------------------------------------------------
// HMMA GEMM: 128x128 tile/CTA, K_eff = 3x256 (hi*hi + hi*lo + lo*hi).
// ---------------------------------------------------------------------------
#define CHUNK_BYTES (128 * 128)
#define BUF_BYTES   (2 * CHUNK_BYTES)
#define GEMM_SMEM   (2 * BUF_BYTES)

__global__ __launch_bounds__(256) void gemm_mma(float* __restrict__ h)
{
    extern __shared__ __align__(128) char smem[];
    const int tid    = threadIdx.x;
    const int wid    = tid >> 5, lane = tid & 31;
    const int warp_m = wid & 3;
    const int warp_n = wid >> 2;
    const int mtile  = blockIdx.x, ntile = blockIdx.y;
    const int rel    = ntile >> 1, n0 = (ntile & 1) << 7;
    const int row0   = mtile * 128;

    uint32_t sbase = smem_u32(smem);

    const char* Ahi = (const char*)g_xhi;
    const char* Alo = (const char*)g_xlo;
    const char* Bhi = (const char*)g_whi + (size_t)rel * 131072;
    const char* Blo = (const char*)g_wlo + (size_t)rel * 131072;

    float acc[2][8][4];
#pragma unroll
    for (int mt = 0; mt < 2; mt++)
#pragma unroll
        for (int nt = 0; nt < 8; nt++)
#pragma unroll
            for (int q = 0; q < 4; q++) acc[mt][nt][q] = 0.f;

    auto load_chunk = [&](int c, int bsel) {
        int seg = c >> 2, kc = c & 3;
        const char* As = (seg == 2) ? Alo : Ahi;
        const char* Bs = (seg == 1) ? Blo : Bhi;
        uint32_t bb = sbase + bsel * BUF_BYTES;
#pragma unroll
        for (int q = 0; q < 8; q++) {
            int s    = tid + (q << 8);
            int part = s >> 10;
            int s10  = s & 1023;
            int row  = s10 >> 3;
            int j    = s10 & 7;
            uint32_t dst = bb + part * CHUNK_BYTES + row * 128 + ((j ^ (row & 7)) << 4);
            const char* src;
            if (part == 0) {
                int gr = row0 + row; if (gr >= NN) gr = NN - 1;
                src = As + (size_t)gr * 512 + kc * 128 + j * 16;
            } else {
                src = Bs + (size_t)(n0 + row) * 512 + kc * 128 + j * 16;
            }
            CP_ASYNC16(dst, src);
        }
        CP_COMMIT();
    };

    load_chunk(0, 0);

    for (int c = 0; c < 12; c++) {
        int b = c & 1;
        if (c + 1 < 12) { load_chunk(c + 1, 1 - b); CP_WAIT(1); }
        else            { CP_WAIT(0); }
        __syncthreads();

        uint32_t Ab = sbase + b * BUF_BYTES;
        uint32_t Bb = Ab + CHUNK_BYTES;

#pragma unroll
        for (int ks = 0; ks < 4; ks++) {
            uint32_t a[2][4];
#pragma unroll
            for (int mt = 0; mt < 2; mt++) {
                int r = warp_m * 32 + mt * 16 + (lane & 15);
                int j = ks * 2 + (lane >> 4);
                LDSM_X4(a[mt], Ab + r * 128 + ((j ^ (r & 7)) << 4));
            }
            uint32_t bf[4][4];
#pragma unroll
            for (int nt2 = 0; nt2 < 4; nt2++) {
                int g = lane >> 3;
                int n = warp_n * 64 + nt2 * 16 + ((g >> 1) << 3) + (lane & 7);
                int j = ks * 2 + (g & 1);
                LDSM_X4(bf[nt2], Bb + n * 128 + ((j ^ (n & 7)) << 4));
            }
#pragma unroll
            for (int mt = 0; mt < 2; mt++)
#pragma unroll
                for (int nt2 = 0; nt2 < 4; nt2++) {
                    MMA16816(acc[mt][nt2 * 2],     a[mt], bf[nt2][0], bf[nt2][1]);
                    MMA16816(acc[mt][nt2 * 2 + 1], a[mt], bf[nt2][2], bf[nt2][3]);
                }
        }
        __syncthreads();
    }

    float* outp = (rel == 0) ? h : (rel == 1 ? g_msg1 : g_msg2);
#pragma unroll
    for (int mt = 0; mt < 2; mt++) {
        int r = row0 + warp_m * 32 + mt * 16 + (lane >> 2);
#pragma unroll
        for (int nt = 0; nt < 8; nt++) {
            int colb = n0 + warp_n * 64 + nt * 8 + 2 * (lane & 3);
            if (r < NN)
                *reinterpret_cast<float2*>(outp + (size_t)r * DIM + colb) =
                    make_float2(acc[mt][nt][0], acc[mt][nt][1]);
            if (r + 8 < NN)
                *reinterpret_cast<float2*>(outp + (size_t)(r + 8) * DIM + colb) =
                    make_float2(acc[mt][nt][2], acc[mt][nt][3]);
        }
    }
}

// ---------------------------------------------------------------------------
// Destination buckets: zero counters, then fill with src ids per (rel, dst)
// ---------------------------------------------------------------------------
__global__ __launch_bounds__(256) void zero_cnt() {
    int i = blockIdx.x * 256 + threadIdx.x;
    if (i < 2 * NN) g_cnt[i] = 0;
}

__global__ __launch_bounds__(256) void bucket_fill(
    const int* __restrict__ src1, const int* __restrict__ dst1,
    const int* __restrict__ src2, const int* __restrict__ dst2,
    float* __restrict__ h)
{
    int e = blockIdx.x * 256 + threadIdx.x;
    if (e >= NE) return;
    int rel = blockIdx.y;
    const int* src = rel ? src2 : src1;
    const int* dst = rel ? dst2 : dst1;
    int s = __ldg(src + e);
    int d = __ldg(dst + e);
    int slot = atomicAdd(&g_cnt[rel * NN + d], 1);
    if (slot < CAP) {
        g_bkt[((size_t)(rel * NN + d)) * CAP + slot] = s;
    } else {
        // overflow fallback (statistically never with CAP=64): atomic into h
        const float* msg = rel ? g_msg2 : g_msg1;
        const float4* sp = reinterpret_cast<const float4*>(msg + (size_t)s * DIM);
        float4*       dp = reinterpret_cast<float4*>(h + (size_t)d * DIM);
        for (int i = 0; i < DIM / 4; i++) red_add_v4(dp + i, sp[i]);
    }
}

// ---------------------------------------------------------------------------
// Gather + finalize: warp per node. acc = h_self[v] + sum msg[srcs]; then
// relu(acc + bias) -> h[v]. No atomics, h read/written exactly once.
// ---------------------------------------------------------------------------
__global__ __launch_bounds__(256) void gather_finalize(
    float* __restrict__ h, const float* __restrict__ bias)
{
    int w    = (blockIdx.x * 256 + threadIdx.x) >> 5;
    int lane = threadIdx.x & 31;
    if (w >= NN) return;

    float4* h4 = reinterpret_cast<float4*>(h) + (size_t)w * 64;
    float4 a0 = h4[lane];
    float4 a1 = h4[lane + 32];

#pragma unroll
    for (int rel = 0; rel < 2; rel++) {
        int n = g_cnt[rel * NN + w];
        if (n > CAP) n = CAP;
        const float4* msg = reinterpret_cast<const float4*>(rel ? g_msg2 : g_msg1);
        const int* bkt = g_bkt + ((size_t)(rel * NN + w)) * CAP;
        int myidx = (lane < n) ? __ldg(bkt + lane) : 0;
        int n1 = n < 32 ? n : 32;
        for (int i = 0; i < n1; i++) {
            int s = __shfl_sync(0xFFFFFFFFu, myidx, i);
            const float4* sp = msg + (size_t)s * 64;
            float4 v0 = sp[lane], v1 = sp[lane + 32];
            a0.x += v0.x; a0.y += v0.y; a0.z += v0.z; a0.w += v0.w;
            a1.x += v1.x; a1.y += v1.y; a1.z += v1.z; a1.w += v1.w;
        }
        for (int i = 32; i < n; i++) {          // rare tail (deg > 32)
            int s = __ldg(bkt + i);
            const float4* sp = msg + (size_t)s * 64;
            float4 v0 = sp[lane], v1 = sp[lane + 32];
            a0.x += v0.x; a0.y += v0.y; a0.z += v0.z; a0.w += v0.w;
            a1.x += v1.x; a1.y += v1.y; a1.z += v1.z; a1.w += v1.w;
        }
    }

    float4 b0 = __ldg(reinterpret_cast<const float4*>(bias) + lane);
    float4 b1 = __ldg(reinterpret_cast<const float4*>(bias) + lane + 32);
    a0.x = fmaxf(a0.x + b0.x, 0.f); a0.y = fmaxf(a0.y + b0.y, 0.f);
    a0.z = fmaxf(a0.z + b0.z, 0.f); a0.w = fmaxf(a0.w + b0.w, 0.f);
    a1.x = fmaxf(a1.x + b1.x, 0.f); a1.y = fmaxf(a1.y + b1.y, 0.f);
    a1.z = fmaxf(a1.z + b1.z, 0.f); a1.w = fmaxf(a1.w + b1.w, 0.f);
    h4[lane]      = a0;
    h4[lane + 32] = a1;
}

// ---------------------------------------------------------------------------
extern "C" void kernel_launch(void* const* d_in, const int* in_sizes, int n_in,
                              void* d_out, int out_size)
{
    const float* x    = (const float*)d_in[0];
    const float* Ws   = (const float*)d_in[1];
    const float* W1   = (const float*)d_in[2];
    const float* W2   = (const float*)d_in[3];
    const float* bias = (const float*)d_in[4];
    const int* src1   = (const int*)d_in[5];
    const int* dst1   = (const int*)d_in[6];
    const int* src2   = (const int*)d_in[7];
    const int* dst2   = (const int*)d_in[8];
    float* h = (float*)d_out;

    cudaFuncSetAttribute(gemm_mma, cudaFuncAttributeMaxDynamicSharedMemorySize, GEMM_SMEM);

    int nx = (int)(((size_t)NN * DIM / 4 + 255) / 256);
    split_x<<<nx, 256>>>(x);
    split_w<<<(3 * DIM * DIM + 255) / 256, 256>>>(Ws, W1, W2);

    dim3 ggrid(MTILES, 6);
    gemm_mma<<<ggrid, 256, GEMM_SMEM>>>(h);

    zero_cnt<<<(2 * NN + 255) / 256, 256>>>();
    dim3 fgrid((NE + 255) / 256, 2);
    bucket_fill<<<fgrid, 256>>>(src1, dst1, src2, dst2, h);

    gather_finalize<<<(NN * 32 + 255) / 256, 256>>>(h, bias);
}

// round 9
// speedup vs baseline: 3.5726x; 1.4890x over previous
#include <cuda_runtime.h>
#include <cuda_fp16.h>
#include <cstdint>

#define NN 100000
#define DIM 256
#define NE 500000
#define MTILES 782            // ceil(NN/128)
#define CAP 64                // bucket capacity per (rel, node); fallback if exceeded

// ---------------------------------------------------------------------------
// __device__ global scratch (allocation-free rule)
// ---------------------------------------------------------------------------
__device__ float g_msg1[(size_t)NN * DIM];
__device__ float g_msg2[(size_t)NN * DIM];
__device__ __half g_xh[(size_t)NN * DIM];
__device__ __half g_wh[3 * DIM * DIM];   // [rel][n][k], 1.1 folded into rel 0
__device__ int g_cnt[2 * NN];
__device__ int g_bkt[(size_t)2 * NN * CAP];

// ---------------------------------------------------------------------------
// PTX helpers (baseline ISA only — harness targets compute_103, no 'a' features)
// ---------------------------------------------------------------------------
__device__ __forceinline__ uint32_t smem_u32(const void* p) {
    uint32_t a;
    asm("{ .reg .u64 t; cvta.to.shared.u64 t, %1; cvt.u32.u64 %0, t; }"
        : "=r"(a) : "l"(p));
    return a;
}

#define CP_ASYNC16(dst, src) \
    asm volatile("cp.async.cg.shared.global [%0], [%1], 16;" :: "r"(dst), "l"(src))
#define CP_COMMIT() asm volatile("cp.async.commit_group;" ::: "memory")
#define CP_WAIT(n)  asm volatile("cp.async.wait_group %0;" :: "n"(n) : "memory")

#define LDSM_X4(r, addr) \
    asm volatile("ldmatrix.sync.aligned.m8n8.x4.shared.b16 {%0,%1,%2,%3}, [%4];" \
        : "=r"((r)[0]), "=r"((r)[1]), "=r"((r)[2]), "=r"((r)[3]) : "r"(addr))

#define MMA16816(d, a, b0, b1) \
    asm volatile("mma.sync.aligned.m16n8k16.row.col.f32.f16.f16.f32 " \
        "{%0,%1,%2,%3}, {%4,%5,%6,%7}, {%8,%9}, {%0,%1,%2,%3};" \
        : "+f"((d)[0]), "+f"((d)[1]), "+f"((d)[2]), "+f"((d)[3]) \
        : "r"((a)[0]), "r"((a)[1]), "r"((a)[2]), "r"((a)[3]), "r"(b0), "r"(b1))

__device__ __forceinline__ void red_add_v4(float4* p, float4 v) {
    asm volatile("red.global.add.v4.f32 [%0], {%1,%2,%3,%4};"
                 :: "l"(p), "f"(v.x), "f"(v.y), "f"(v.z), "f"(v.w)
                 : "memory");
}

// ---------------------------------------------------------------------------
// Prep: convert x to fp16
// ---------------------------------------------------------------------------
__global__ __launch_bounds__(256) void conv_x(const float* __restrict__ x) {
    size_t i = (size_t)blockIdx.x * 256 + threadIdx.x;   // per float4
    if (i >= (size_t)NN * DIM / 4) return;
    float4 v = reinterpret_cast<const float4*>(x)[i];
    __half2 h01 = __floats2half2_rn(v.x, v.y);
    __half2 h23 = __floats2half2_rn(v.z, v.w);
    reinterpret_cast<__half2*>(g_xh)[2 * i]     = h01;
    reinterpret_cast<__half2*>(g_xh)[2 * i + 1] = h23;
}

// Prep: transpose + convert W  (g_wh[rel*65536 + n*256 + k] = fp16(Weff[k][n]))
__global__ __launch_bounds__(256) void conv_w(
    const float* __restrict__ Ws, const float* __restrict__ W1,
    const float* __restrict__ W2)
{
    int idx = blockIdx.x * 256 + threadIdx.x;            // 0 .. 196607
    if (idx >= 3 * DIM * DIM) return;
    int rel = idx >> 16;
    int r   = idx & 65535;
    int n   = r >> 8;
    int k   = r & 255;
    const float* W = (rel == 0) ? Ws : (rel == 1) ? W1 : W2;
    float v = W[k * DIM + n] * ((rel == 0) ? 1.1f : 1.0f);
    g_wh[idx] = __float2half_rn(v);
}

// ---------------------------------------------------------------------------
// HMMA GEMM: 128x128 tile/CTA, K = 256, single-product fp16.
// grid (6, 782): x = ntile (rel*2 + nhalf)  [adjacent bids share the A tile
// -> L2 reuse], y = mtile.
// ---------------------------------------------------------------------------
#define CHUNK_BYTES (128 * 128)
#define BUF_BYTES   (2 * CHUNK_BYTES)
#define GEMM_SMEM   (2 * BUF_BYTES)

__global__ __launch_bounds__(256) void gemm_mma(float* __restrict__ h)
{
    extern __shared__ __align__(128) char smem[];
    const int tid    = threadIdx.x;
    const int wid    = tid >> 5, lane = tid & 31;
    const int warp_m = wid & 3;
    const int warp_n = wid >> 2;
    const int ntile  = blockIdx.x, mtile = blockIdx.y;
    const int rel    = ntile >> 1, n0 = (ntile & 1) << 7;
    const int row0   = mtile * 128;

    uint32_t sbase = sbase = smem_u32(smem);

    const char* Asrc = (const char*)g_xh;
    const char* Bsrc = (const char*)g_wh + (size_t)rel * 131072;

    float acc[2][8][4];
#pragma unroll
    for (int mt = 0; mt < 2; mt++)
#pragma unroll
        for (int nt = 0; nt < 8; nt++)
#pragma unroll
            for (int q = 0; q < 4; q++) acc[mt][nt][q] = 0.f;

    // load one 64-K chunk (A 128x64, B 128x64 fp16) into buffer bsel
    auto load_chunk = [&](int kc, int bsel) {
        uint32_t bb = sbase + bsel * BUF_BYTES;
#pragma unroll
        for (int q = 0; q < 8; q++) {
            int s    = tid + (q << 8);          // 0..2047 16B segments
            int part = s >> 10;                 // 0:A 1:B
            int s10  = s & 1023;
            int row  = s10 >> 3;                // 0..127
            int j    = s10 & 7;                 // 16B seg within 128B row
            uint32_t dst = bb + part * CHUNK_BYTES + row * 128 + ((j ^ (row & 7)) << 4);
            const char* src;
            if (part == 0) {
                int gr = row0 + row; if (gr >= NN) gr = NN - 1;
                src = Asrc + (size_t)gr * 512 + kc * 128 + j * 16;
            } else {
                src = Bsrc + (size_t)(n0 + row) * 512 + kc * 128 + j * 16;
            }
            CP_ASYNC16(dst, src);
        }
        CP_COMMIT();
    };

    load_chunk(0, 0);

    for (int c = 0; c < 4; c++) {
        int b = c & 1;
        if (c + 1 < 4) { load_chunk(c + 1, 1 - b); CP_WAIT(1); }
        else           { CP_WAIT(0); }
        __syncthreads();

        uint32_t Ab = sbase + b * BUF_BYTES;
        uint32_t Bb = Ab + CHUNK_BYTES;

#pragma unroll
        for (int ks = 0; ks < 4; ks++) {         // K=16 steps within 64-K chunk
            uint32_t a[2][4];
#pragma unroll
            for (int mt = 0; mt < 2; mt++) {
                int r = warp_m * 32 + mt * 16 + (lane & 15);
                int j = ks * 2 + (lane >> 4);
                LDSM_X4(a[mt], Ab + r * 128 + ((j ^ (r & 7)) << 4));
            }
            uint32_t bf[4][4];
#pragma unroll
            for (int nt2 = 0; nt2 < 4; nt2++) {
                int g = lane >> 3;
                int n = warp_n * 64 + nt2 * 16 + ((g >> 1) << 3) + (lane & 7);
                int j = ks * 2 + (g & 1);
                LDSM_X4(bf[nt2], Bb + n * 128 + ((j ^ (n & 7)) << 4));
            }
#pragma unroll
            for (int mt = 0; mt < 2; mt++)
#pragma unroll
                for (int nt2 = 0; nt2 < 4; nt2++) {
                    MMA16816(acc[mt][nt2 * 2],     a[mt], bf[nt2][0], bf[nt2][1]);
                    MMA16816(acc[mt][nt2 * 2 + 1], a[mt], bf[nt2][2], bf[nt2][3]);
                }
        }
        __syncthreads();
    }

    float* outp = (rel == 0) ? h : (rel == 1 ? g_msg1 : g_msg2);
#pragma unroll
    for (int mt = 0; mt < 2; mt++) {
        int r = row0 + warp_m * 32 + mt * 16 + (lane >> 2);
#pragma unroll
        for (int nt = 0; nt < 8; nt++) {
            int colb = n0 + warp_n * 64 + nt * 8 + 2 * (lane & 3);
            if (r < NN)
                *reinterpret_cast<float2*>(outp + (size_t)r * DIM + colb) =
                    make_float2(acc[mt][nt][0], acc[mt][nt][1]);
            if (r + 8 < NN)
                *reinterpret_cast<float2*>(outp + (size_t)(r + 8) * DIM + colb) =
                    make_float2(acc[mt][nt][2], acc[mt][nt][3]);
        }
    }
}

// ---------------------------------------------------------------------------
// Destination buckets: zero counters, then fill with src ids per (rel, dst)
// ---------------------------------------------------------------------------
__global__ __launch_bounds__(256) void zero_cnt() {
    int i = blockIdx.x * 256 + threadIdx.x;
    if (i < 2 * NN) g_cnt[i] = 0;
}

__global__ __launch_bounds__(256) void bucket_fill(
    const int* __restrict__ src1, const int* __restrict__ dst1,
    const int* __restrict__ src2, const int* __restrict__ dst2,
    float* __restrict__ h)
{
    int e = blockIdx.x * 256 + threadIdx.x;
    if (e >= NE) return;
    int rel = blockIdx.y;
    const int* src = rel ? src2 : src1;
    const int* dst = rel ? dst2 : dst1;
    int s = __ldg(src + e);
    int d = __ldg(dst + e);
    int slot = atomicAdd(&g_cnt[rel * NN + d], 1);
    if (slot < CAP) {
        g_bkt[((size_t)(rel * NN + d)) * CAP + slot] = s;
    } else {
        // overflow fallback (statistically never with CAP=64): atomic into h
        const float* msg = rel ? g_msg2 : g_msg1;
        const float4* sp = reinterpret_cast<const float4*>(msg + (size_t)s * DIM);
        float4*       dp = reinterpret_cast<float4*>(h + (size_t)d * DIM);
        for (int i = 0; i < DIM / 4; i++) red_add_v4(dp + i, sp[i]);
    }
}

// ---------------------------------------------------------------------------
// Gather + finalize: warp per node. acc = h_self[v] + sum msg[srcs]; then
// relu(acc + bias) -> h[v]. No atomics, h read/written exactly once.
// ---------------------------------------------------------------------------
__global__ __launch_bounds__(256) void gather_finalize(
    float* __restrict__ h, const float* __restrict__ bias)
{
    int w    = (blockIdx.x * 256 + threadIdx.x) >> 5;
    int lane = threadIdx.x & 31;
    if (w >= NN) return;

    float4* h4 = reinterpret_cast<float4*>(h) + (size_t)w * 64;
    float4 a0 = h4[lane];
    float4 a1 = h4[lane + 32];

#pragma unroll
    for (int rel = 0; rel < 2; rel++) {
        int n = g_cnt[rel * NN + w];
        if (n > CAP) n = CAP;
        const float4* msg = reinterpret_cast<const float4*>(rel ? g_msg2 : g_msg1);
        const int* bkt = g_bkt + ((size_t)(rel * NN + w)) * CAP;
        int myidx = (lane < n) ? __ldg(bkt + lane) : 0;
        int n1 = n < 32 ? n : 32;
        for (int i = 0; i < n1; i++) {
            int s = __shfl_sync(0xFFFFFFFFu, myidx, i);
            const float4* sp = msg + (size_t)s * 64;
            float4 v0 = sp[lane], v1 = sp[lane + 32];
            a0.x += v0.x; a0.y += v0.y; a0.z += v0.z; a0.w += v0.w;
            a1.x += v1.x; a1.y += v1.y; a1.z += v1.z; a1.w += v1.w;
        }
        for (int i = 32; i < n; i++) {          // rare tail (deg > 32)
            int s = __ldg(bkt + i);
            const float4* sp = msg + (size_t)s * 64;
            float4 v0 = sp[lane], v1 = sp[lane + 32];
            a0.x += v0.x; a0.y += v0.y; a0.z += v0.z; a0.w += v0.w;
            a1.x += v1.x; a1.y += v1.y; a1.z += v1.z; a1.w += v1.w;
        }
    }

    float4 b0 = __ldg(reinterpret_cast<const float4*>(bias) + lane);
    float4 b1 = __ldg(reinterpret_cast<const float4*>(bias) + lane + 32);
    a0.x = fmaxf(a0.x + b0.x, 0.f); a0.y = fmaxf(a0.y + b0.y, 0.f);
    a0.z = fmaxf(a0.z + b0.z, 0.f); a0.w = fmaxf(a0.w + b0.w, 0.f);
    a1.x = fmaxf(a1.x + b1.x, 0.f); a1.y = fmaxf(a1.y + b1.y, 0.f);
    a1.z = fmaxf(a1.z + b1.z, 0.f); a1.w = fmaxf(a1.w + b1.w, 0.f);
    h4[lane]      = a0;
    h4[lane + 32] = a1;
}

// ---------------------------------------------------------------------------
extern "C" void kernel_launch(void* const* d_in, const int* in_sizes, int n_in,
                              void* d_out, int out_size)
{
    const float* x    = (const float*)d_in[0];
    const float* Ws   = (const float*)d_in[1];
    const float* W1   = (const float*)d_in[2];
    const float* W2   = (const float*)d_in[3];
    const float* bias = (const float*)d_in[4];
    const int* src1   = (const int*)d_in[5];
    const int* dst1   = (const int*)d_in[6];
    const int* src2   = (const int*)d_in[7];
    const int* dst2   = (const int*)d_in[8];
    float* h = (float*)d_out;

    cudaFuncSetAttribute(gemm_mma, cudaFuncAttributeMaxDynamicSharedMemorySize, GEMM_SMEM);

    int nx = (int)(((size_t)NN * DIM / 4 + 255) / 256);
    conv_x<<<nx, 256>>>(x);
    conv_w<<<(3 * DIM * DIM + 255) / 256, 256>>>(Ws, W1, W2);

    dim3 ggrid(6, MTILES);
    gemm_mma<<<ggrid, 256, GEMM_SMEM>>>(h);

    zero_cnt<<<(2 * NN + 255) / 256, 256>>>();
    dim3 fgrid((NE + 255) / 256, 2);
    bucket_fill<<<fgrid, 256>>>(src1, dst1, src2, dst2, h);

    gather_finalize<<<(NN * 32 + 255) / 256, 256>>>(h, bias);
}

// round 11
// speedup vs baseline: 4.1955x; 1.1743x over previous
#include <cuda_runtime.h>
#include <cuda_fp16.h>
#include <cstdint>

#define NN 100000
#define DIM 256
#define NE 500000
#define MTILES 782            // ceil(NN/128)
#define CAP 64                // bucket capacity per (rel, node); fallback if exceeded

// ---------------------------------------------------------------------------
// __device__ global scratch (allocation-free rule)
// ---------------------------------------------------------------------------
__device__ __half g_msg1[(size_t)NN * DIM];     // fp16 messages
__device__ __half g_msg2[(size_t)NN * DIM];
__device__ __half g_xh[(size_t)NN * DIM];
__device__ __half g_wh[3 * DIM * DIM];          // [rel][n][k], 1.1 folded into rel 0
__device__ int g_cnt[2 * NN];
__device__ int g_bkt[(size_t)2 * NN * CAP];

// ---------------------------------------------------------------------------
// PTX helpers (baseline ISA only — harness targets compute_103, no 'a' features)
// ---------------------------------------------------------------------------
__device__ __forceinline__ uint32_t smem_u32(const void* p) {
    uint32_t a;
    asm("{ .reg .u64 t; cvta.to.shared.u64 t, %1; cvt.u32.u64 %0, t; }"
        : "=r"(a) : "l"(p));
    return a;
}

#define CP_ASYNC16(dst, src) \
    asm volatile("cp.async.cg.shared.global [%0], [%1], 16;" :: "r"(dst), "l"(src))
#define CP_COMMIT() asm volatile("cp.async.commit_group;" ::: "memory")
#define CP_WAIT(n)  asm volatile("cp.async.wait_group %0;" :: "n"(n) : "memory")

#define LDSM_X4(r, addr) \
    asm volatile("ldmatrix.sync.aligned.m8n8.x4.shared.b16 {%0,%1,%2,%3}, [%4];" \
        : "=r"((r)[0]), "=r"((r)[1]), "=r"((r)[2]), "=r"((r)[3]) : "r"(addr))

#define MMA16816(d, a, b0, b1) \
    asm volatile("mma.sync.aligned.m16n8k16.row.col.f32.f16.f16.f32 " \
        "{%0,%1,%2,%3}, {%4,%5,%6,%7}, {%8,%9}, {%0,%1,%2,%3};" \
        : "+f"((d)[0]), "+f"((d)[1]), "+f"((d)[2]), "+f"((d)[3]) \
        : "r"((a)[0]), "r"((a)[1]), "r"((a)[2]), "r"((a)[3]), "r"(b0), "r"(b1))

__device__ __forceinline__ void red_add_v4(float4* p, float4 v) {
    asm volatile("red.global.add.v4.f32 [%0], {%1,%2,%3,%4};"
                 :: "l"(p), "f"(v.x), "f"(v.y), "f"(v.z), "f"(v.w)
                 : "memory");
}

// ---------------------------------------------------------------------------
// Prep: convert x to fp16
// ---------------------------------------------------------------------------
__global__ __launch_bounds__(256) void conv_x(const float* __restrict__ x) {
    size_t i = (size_t)blockIdx.x * 256 + threadIdx.x;   // per float4
    if (i >= (size_t)NN * DIM / 4) return;
    float4 v = reinterpret_cast<const float4*>(x)[i];
    __half2 h01 = __floats2half2_rn(v.x, v.y);
    __half2 h23 = __floats2half2_rn(v.z, v.w);
    reinterpret_cast<__half2*>(g_xh)[2 * i]     = h01;
    reinterpret_cast<__half2*>(g_xh)[2 * i + 1] = h23;
}

// Prep: transpose + convert W  (g_wh[rel*65536 + n*256 + k] = fp16(Weff[k][n]))
__global__ __launch_bounds__(256) void conv_w(
    const float* __restrict__ Ws, const float* __restrict__ W1,
    const float* __restrict__ W2)
{
    int idx = blockIdx.x * 256 + threadIdx.x;            // 0 .. 196607
    if (idx >= 3 * DIM * DIM) return;
    int rel = idx >> 16;
    int r   = idx & 65535;
    int n   = r >> 8;
    int k   = r & 255;
    const float* W = (rel == 0) ? Ws : (rel == 1) ? W1 : W2;
    float v = W[k * DIM + n] * ((rel == 0) ? 1.1f : 1.0f);
    g_wh[idx] = __float2half_rn(v);
}

// ---------------------------------------------------------------------------
// HMMA GEMM: 128x128 tile/CTA, K = 256, fp16 inputs, fp32 accum.
// grid (6, 782): x = ntile (rel*2 + nhalf) -> adjacent bids share A via L2.
// rel 0 writes fp32 to h; rel 1/2 write fp16 to g_msg1/g_msg2.
// ---------------------------------------------------------------------------
#define CHUNK_BYTES (128 * 128)
#define BUF_BYTES   (2 * CHUNK_BYTES)
#define GEMM_SMEM   (2 * BUF_BYTES)

__global__ __launch_bounds__(256) void gemm_mma(float* __restrict__ h)
{
    extern __shared__ __align__(128) char smem[];
    const int tid    = threadIdx.x;
    const int wid    = tid >> 5, lane = tid & 31;
    const int warp_m = wid & 3;
    const int warp_n = wid >> 2;
    const int ntile  = blockIdx.x, mtile = blockIdx.y;
    const int rel    = ntile >> 1, n0 = (ntile & 1) << 7;
    const int row0   = mtile * 128;

    uint32_t sbase = smem_u32(smem);

    const char* Asrc = (const char*)g_xh;
    const char* Bsrc = (const char*)g_wh + (size_t)rel * 131072;

    float acc[2][8][4];
#pragma unroll
    for (int mt = 0; mt < 2; mt++)
#pragma unroll
        for (int nt = 0; nt < 8; nt++)
#pragma unroll
            for (int q = 0; q < 4; q++) acc[mt][nt][q] = 0.f;

    auto load_chunk = [&](int kc, int bsel) {
        uint32_t bb = sbase + bsel * BUF_BYTES;
#pragma unroll
        for (int q = 0; q < 8; q++) {
            int s    = tid + (q << 8);          // 0..2047 16B segments
            int part = s >> 10;                 // 0:A 1:B
            int s10  = s & 1023;
            int row  = s10 >> 3;
            int j    = s10 & 7;
            uint32_t dst = bb + part * CHUNK_BYTES + row * 128 + ((j ^ (row & 7)) << 4);
            const char* src;
            if (part == 0) {
                int gr = row0 + row; if (gr >= NN) gr = NN - 1;
                src = Asrc + (size_t)gr * 512 + kc * 128 + j * 16;
            } else {
                src = Bsrc + (size_t)(n0 + row) * 512 + kc * 128 + j * 16;
            }
            CP_ASYNC16(dst, src);
        }
        CP_COMMIT();
    };

    load_chunk(0, 0);

    for (int c = 0; c < 4; c++) {
        int b = c & 1;
        if (c + 1 < 4) { load_chunk(c + 1, 1 - b); CP_WAIT(1); }
        else           { CP_WAIT(0); }
        __syncthreads();

        uint32_t Ab = sbase + b * BUF_BYTES;
        uint32_t Bb = Ab + CHUNK_BYTES;

#pragma unroll
        for (int ks = 0; ks < 4; ks++) {
            uint32_t a[2][4];
#pragma unroll
            for (int mt = 0; mt < 2; mt++) {
                int r = warp_m * 32 + mt * 16 + (lane & 15);
                int j = ks * 2 + (lane >> 4);
                LDSM_X4(a[mt], Ab + r * 128 + ((j ^ (r & 7)) << 4));
            }
            uint32_t bf[4][4];
#pragma unroll
            for (int nt2 = 0; nt2 < 4; nt2++) {
                int g = lane >> 3;
                int n = warp_n * 64 + nt2 * 16 + ((g >> 1) << 3) + (lane & 7);
                int j = ks * 2 + (g & 1);
                LDSM_X4(bf[nt2], Bb + n * 128 + ((j ^ (n & 7)) << 4));
            }
#pragma unroll
            for (int mt = 0; mt < 2; mt++)
#pragma unroll
                for (int nt2 = 0; nt2 < 4; nt2++) {
                    MMA16816(acc[mt][nt2 * 2],     a[mt], bf[nt2][0], bf[nt2][1]);
                    MMA16816(acc[mt][nt2 * 2 + 1], a[mt], bf[nt2][2], bf[nt2][3]);
                }
        }
        __syncthreads();
    }

    if (rel == 0) {
#pragma unroll
        for (int mt = 0; mt < 2; mt++) {
            int r = row0 + warp_m * 32 + mt * 16 + (lane >> 2);
#pragma unroll
            for (int nt = 0; nt < 8; nt++) {
                int colb = n0 + warp_n * 64 + nt * 8 + 2 * (lane & 3);
                if (r < NN)
                    *reinterpret_cast<float2*>(h + (size_t)r * DIM + colb) =
                        make_float2(acc[mt][nt][0], acc[mt][nt][1]);
                if (r + 8 < NN)
                    *reinterpret_cast<float2*>(h + (size_t)(r + 8) * DIM + colb) =
                        make_float2(acc[mt][nt][2], acc[mt][nt][3]);
            }
        }
    } else {
        __half* mp = (rel == 1) ? g_msg1 : g_msg2;
#pragma unroll
        for (int mt = 0; mt < 2; mt++) {
            int r = row0 + warp_m * 32 + mt * 16 + (lane >> 2);
#pragma unroll
            for (int nt = 0; nt < 8; nt++) {
                int colb = n0 + warp_n * 64 + nt * 8 + 2 * (lane & 3);
                if (r < NN)
                    *reinterpret_cast<__half2*>(mp + (size_t)r * DIM + colb) =
                        __floats2half2_rn(acc[mt][nt][0], acc[mt][nt][1]);
                if (r + 8 < NN)
                    *reinterpret_cast<__half2*>(mp + (size_t)(r + 8) * DIM + colb) =
                        __floats2half2_rn(acc[mt][nt][2], acc[mt][nt][3]);
            }
        }
    }
}

// ---------------------------------------------------------------------------
// Destination buckets
// ---------------------------------------------------------------------------
__global__ __launch_bounds__(256) void zero_cnt() {
    int i = blockIdx.x * 256 + threadIdx.x;
    if (i < 2 * NN) g_cnt[i] = 0;
}

__global__ __launch_bounds__(256) void bucket_fill(
    const int* __restrict__ src1, const int* __restrict__ dst1,
    const int* __restrict__ src2, const int* __restrict__ dst2,
    float* __restrict__ h)
{
    int e = blockIdx.x * 256 + threadIdx.x;
    if (e >= NE) return;
    int rel = blockIdx.y;
    const int* src = rel ? src2 : src1;
    const int* dst = rel ? dst2 : dst1;
    int s = __ldg(src + e);
    int d = __ldg(dst + e);
    int slot = atomicAdd(&g_cnt[rel * NN + d], 1);
    if (slot < CAP) {
        g_bkt[((size_t)(rel * NN + d)) * CAP + slot] = s;
    } else {
        // overflow fallback (statistically never with CAP=64): atomic into h
        const __half2* sp = reinterpret_cast<const __half2*>(
            (rel ? g_msg2 : g_msg1) + (size_t)s * DIM);
        float4* dp = reinterpret_cast<float4*>(h + (size_t)d * DIM);
        for (int i = 0; i < DIM / 4; i++) {
            float2 p0 = __half22float2(sp[2 * i]);
            float2 p1 = __half22float2(sp[2 * i + 1]);
            red_add_v4(dp + i, make_float4(p0.x, p0.y, p1.x, p1.y));
        }
    }
}

// ---------------------------------------------------------------------------
// Gather + finalize: warp per node; lane owns cols [8L, 8L+8).
// acc = h_self[v] + sum fp16 msg rows; relu(acc + bias) -> h[v].
// ---------------------------------------------------------------------------
__global__ __launch_bounds__(256) void gather_finalize(
    float* __restrict__ h, const float* __restrict__ bias)
{
    int w    = (blockIdx.x * 256 + threadIdx.x) >> 5;
    int lane = threadIdx.x & 31;
    if (w >= NN) return;

    float4* h4 = reinterpret_cast<float4*>(h) + (size_t)w * 64;
    float4 a0 = h4[2 * lane];
    float4 a1 = h4[2 * lane + 1];

#pragma unroll
    for (int rel = 0; rel < 2; rel++) {
        int n = g_cnt[rel * NN + w];
        if (n > CAP) n = CAP;
        const uint4* msg = reinterpret_cast<const uint4*>(rel ? g_msg2 : g_msg1);
        const int* bkt = g_bkt + ((size_t)(rel * NN + w)) * CAP;
        int myidx = (lane < n) ? __ldg(bkt + lane) : 0;
        int n1 = n < 32 ? n : 32;
        for (int i = 0; i < n1; i++) {
            int s = __shfl_sync(0xFFFFFFFFu, myidx, i);
            uint4 v = msg[(size_t)s * 32 + lane];       // 8 halves = cols 8L..8L+7
            float2 p0 = __half22float2(*reinterpret_cast<const __half2*>(&v.x));
            float2 p1 = __half22float2(*reinterpret_cast<const __half2*>(&v.y));
            float2 p2 = __half22float2(*reinterpret_cast<const __half2*>(&v.z));
            float2 p3 = __half22float2(*reinterpret_cast<const __half2*>(&v.w));
            a0.x += p0.x; a0.y += p0.y; a0.z += p1.x; a0.w += p1.y;
            a1.x += p2.x; a1.y += p2.y; a1.z += p3.x; a1.w += p3.y;
        }
        for (int i = 32; i < n; i++) {                  // rare tail (deg > 32)
            int s = __ldg(bkt + i);
            uint4 v = msg[(size_t)s * 32 + lane];
            float2 p0 = __half22float2(*reinterpret_cast<const __half2*>(&v.x));
            float2 p1 = __half22float2(*reinterpret_cast<const __half2*>(&v.y));
            float2 p2 = __half22float2(*reinterpret_cast<const __half2*>(&v.z));
            float2 p3 = __half22float2(*reinterpret_cast<const __half2*>(&v.w));
            a0.x += p0.x; a0.y += p0.y; a0.z += p1.x; a0.w += p1.y;
            a1.x += p2.x; a1.y += p2.y; a1.z += p3.x; a1.w += p3.y;
        }
    }

    const float4* b4 = reinterpret_cast<const float4*>(bias);
    float4 b0 = __ldg(b4 + 2 * lane);
    float4 b1 = __ldg(b4 + 2 * lane + 1);
    a0.x = fmaxf(a0.x + b0.x, 0.f); a0.y = fmaxf(a0.y + b0.y, 0.f);
    a0.z = fmaxf(a0.z + b0.z, 0.f); a0.w = fmaxf(a0.w + b0.w, 0.f);
    a1.x = fmaxf(a1.x + b1.x, 0.f); a1.y = fmaxf(a1.y + b1.y, 0.f);
    a1.z = fmaxf(a1.z + b1.z, 0.f); a1.w = fmaxf(a1.w + b1.w, 0.f);
    h4[2 * lane]     = a0;
    h4[2 * lane + 1] = a1;
}

// ---------------------------------------------------------------------------
extern "C" void kernel_launch(void* const* d_in, const int* in_sizes, int n_in,
                              void* d_out, int out_size)
{
    const float* x    = (const float*)d_in[0];
    const float* Ws   = (const float*)d_in[1];
    const float* W1   = (const float*)d_in[2];
    const float* W2   = (const float*)d_in[3];
    const float* bias = (const float*)d_in[4];
    const int* src1   = (const int*)d_in[5];
    const int* dst1   = (const int*)d_in[6];
    const int* src2   = (const int*)d_in[7];
    const int* dst2   = (const int*)d_in[8];
    float* h = (float*)d_out;

    cudaFuncSetAttribute(gemm_mma, cudaFuncAttributeMaxDynamicSharedMemorySize, GEMM_SMEM);

    int nx = (int)(((size_t)NN * DIM / 4 + 255) / 256);
    conv_x<<<nx, 256>>>(x);
    conv_w<<<(3 * DIM * DIM + 255) / 256, 256>>>(Ws, W1, W2);

    dim3 ggrid(6, MTILES);
    gemm_mma<<<ggrid, 256, GEMM_SMEM>>>(h);

    zero_cnt<<<(2 * NN + 255) / 256, 256>>>();
    dim3 fgrid((NE + 255) / 256, 2);
    bucket_fill<<<fgrid, 256>>>(src1, dst1, src2, dst2, h);

    gather_finalize<<<(NN * 32 + 255) / 256, 256>>>(h, bias);
}